// round 1
// baseline (speedup 1.0000x reference)
#include <cuda_runtime.h>
#include <cuda_bf16.h>

#define B_    4
#define N_    2048
#define CIN_  256
#define COUT_ 64
#define H_    8
#define ALPHA 0.2f

// Scratch (allocation-free rule: __device__ globals)
__device__ float g_hidden[(size_t)B_ * H_ * N_ * COUT_]; // 16 MB, [b][h][n][o]
__device__ float g_s1[B_ * H_ * N_];
__device__ float g_s2[B_ * H_ * N_];
__device__ float g_s2max[B_ * H_];

// ---------------------------------------------------------------------------
// Kernel 1: hidden[b,h,n,o] = sum_i x[b,n,i] * W[h,o,i]
// Per-b GEMM: C[2048, 512] = X[2048,256] @ Wf[512,256]^T, Wf = W viewed [512,256]
// BM=BN=64, BK=32, 256 threads, 4x4 per thread.
// ---------------------------------------------------------------------------
__global__ void gemm_hidden(const float* __restrict__ x,
                            const float* __restrict__ Wf) {
    const int b    = blockIdx.z;
    const int m0   = blockIdx.x * 64;
    const int col0 = blockIdx.y * 64;          // == h*64 (tile aligned to head)
    __shared__ float As[32][68];               // [k][m], 68 keeps 16B alignment
    __shared__ float Bs[32][68];               // [k][n]
    const int t  = threadIdx.x;
    const int tx = t & 15, ty = t >> 4;
    float acc[4][4] = {};

    const float* xb = x + (size_t)b * N_ * CIN_;

    for (int k0 = 0; k0 < CIN_; k0 += 32) {
#pragma unroll
        for (int r = 0; r < 2; r++) {
            int fidx = t + r * 256;            // 0..511
            int row  = fidx >> 3;              // 0..63
            int c4   = (fidx & 7) * 4;         // 0..28
            float4 v = *(const float4*)&xb[(size_t)(m0 + row) * CIN_ + k0 + c4];
            As[c4 + 0][row] = v.x; As[c4 + 1][row] = v.y;
            As[c4 + 2][row] = v.z; As[c4 + 3][row] = v.w;
            float4 w = *(const float4*)&Wf[(size_t)(col0 + row) * CIN_ + k0 + c4];
            Bs[c4 + 0][row] = w.x; Bs[c4 + 1][row] = w.y;
            Bs[c4 + 2][row] = w.z; Bs[c4 + 3][row] = w.w;
        }
        __syncthreads();
#pragma unroll
        for (int kk = 0; kk < 32; kk++) {
            float4 rm = *(const float4*)&As[kk][ty * 4];
            float4 rn = *(const float4*)&Bs[kk][tx * 4];
            float am[4] = {rm.x, rm.y, rm.z, rm.w};
            float an[4] = {rn.x, rn.y, rn.z, rn.w};
#pragma unroll
            for (int i = 0; i < 4; i++)
#pragma unroll
                for (int j = 0; j < 4; j++)
                    acc[i][j] += am[i] * an[j];
        }
        __syncthreads();
    }

    const int h = col0 >> 6;
    float* dst = g_hidden + ((size_t)(b * H_ + h) * N_) * COUT_;
#pragma unroll
    for (int i = 0; i < 4; i++) {
        int m = m0 + ty * 4 + i;
        float4 o = make_float4(acc[i][0], acc[i][1], acc[i][2], acc[i][3]);
        *(float4*)&dst[(size_t)m * COUT_ + tx * 4] = o;
    }
}

// ---------------------------------------------------------------------------
// Kernel 2: s1/s2 = <hidden_row, a[h,0,:]>, <hidden_row, a[h,1,:]>
// One warp per (b,h,n) row.
// ---------------------------------------------------------------------------
__global__ void attn_scores(const float* __restrict__ a) {
    int gw   = blockIdx.x * 8 + (threadIdx.x >> 5);   // row id over B*H*N
    int lane = threadIdx.x & 31;
    int bh   = gw >> 11;                              // / N_
    int h    = bh & 7;
    const float* hrow = g_hidden + (size_t)gw * COUT_;
    float v0 = hrow[lane], v1 = hrow[lane + 32];
    const float* ah = a + h * 2 * COUT_;
    float p1 = v0 * ah[lane]      + v1 * ah[lane + 32];
    float p2 = v0 * ah[64 + lane] + v1 * ah[96 + lane];
#pragma unroll
    for (int off = 16; off > 0; off >>= 1) {
        p1 += __shfl_xor_sync(0xffffffff, p1, off);
        p2 += __shfl_xor_sync(0xffffffff, p2, off);
    }
    if (lane == 0) { g_s1[gw] = p1; g_s2[gw] = p2; }
}

// ---------------------------------------------------------------------------
// Kernel 3: per (b,h) unmasked max of s2 (upper bound for softmax stability)
// ---------------------------------------------------------------------------
__global__ void s2max_kernel() {
    __shared__ float red[256];
    int bh = blockIdx.x;
    const float* s2 = g_s2 + bh * N_;
    float m = -1e30f;
    for (int j = threadIdx.x; j < N_; j += 256) m = fmaxf(m, s2[j]);
    red[threadIdx.x] = m;
    __syncthreads();
    for (int s = 128; s > 0; s >>= 1) {
        if (threadIdx.x < s) red[threadIdx.x] = fmaxf(red[threadIdx.x], red[threadIdx.x + s]);
        __syncthreads();
    }
    if (threadIdx.x == 0) g_s2max[bh] = red[0];
}

// ---------------------------------------------------------------------------
// Kernel 4: fused mask + softmax + (attn @ hidden) + bias + relu
// Block: 16 query rows of one (b,h). 256 threads = 16 rows x 16 channel-quads.
// Loop j in tiles of 64: stage hidden tile + weight tile in smem.
// ---------------------------------------------------------------------------
__global__ void attn_av(const int* __restrict__ adj,
                        const float* __restrict__ bias,
                        float* __restrict__ out) {
    const int b  = blockIdx.z, h = blockIdx.y;
    const int i0 = blockIdx.x * 16;
    const int bh = b * H_ + h;

    __shared__ float hid_s[64][64];    // [jj][c]
    __shared__ float w_s[16][64];      // [i][jj]
    __shared__ float s1_s[16], M_s[16];

    const int t = threadIdx.x;
    if (t < 16) {
        float s1v = g_s1[bh * N_ + i0 + t];
        float e = s1v + g_s2max[bh];
        M_s[t]  = (e >= 0.f) ? e : ALPHA * e;   // leaky is monotone: valid max bound
        s1_s[t] = s1v;
    }
    __syncthreads();

    const int i  = t >> 4;             // query row within block
    const int cg = t & 15;             // channel quad
    float4 acc = make_float4(0.f, 0.f, 0.f, 0.f);
    float wsum = 0.f;

    const float* hidbh = g_hidden + (size_t)bh * N_ * COUT_;
    const float* s2bh  = g_s2 + bh * N_;
    const int*   adjb  = adj + ((size_t)(b * N_ + i0)) * N_;

    for (int j0 = 0; j0 < N_; j0 += 64) {
        // stage hidden tile [64 x 64]
#pragma unroll
        for (int r = 0; r < 4; r++) {
            int idx = t + r * 256;
            int row = idx >> 4, c4 = (idx & 15) * 4;
            *(float4*)&hid_s[row][c4] =
                *(const float4*)&hidbh[(size_t)(j0 + row) * COUT_ + c4];
        }
        // compute weights [16 x 64]
#pragma unroll
        for (int r = 0; r < 4; r++) {
            int idx = t + r * 256;
            int wi = idx >> 6, jj = idx & 63;
            float e = s1_s[wi] + s2bh[j0 + jj];
            float l = (e >= 0.f) ? e : ALPHA * e;
            int av  = adjb[(size_t)wi * N_ + j0 + jj];
            w_s[wi][jj] = (av > 0) ? __expf(l - M_s[wi]) : 0.f;
        }
        __syncthreads();

#pragma unroll 8
        for (int jj = 0; jj < 64; jj++) {
            float  wv = w_s[i][jj];
            float4 hv = *(const float4*)&hid_s[jj][cg * 4];
            acc.x += wv * hv.x; acc.y += wv * hv.y;
            acc.z += wv * hv.z; acc.w += wv * hv.w;
            wsum  += wv;
        }
        __syncthreads();
    }

    float inv = 1.f / wsum;
    int c = cg * 4;
    float4 bv = *(const float4*)&bias[h * COUT_ + c];
    float4 o;
    o.x = fmaxf(acc.x * inv + bv.x, 0.f);
    o.y = fmaxf(acc.y * inv + bv.y, 0.f);
    o.z = fmaxf(acc.z * inv + bv.z, 0.f);
    o.w = fmaxf(acc.w * inv + bv.w, 0.f);
    *(float4*)&out[((size_t)(b * N_ + i0 + i)) * (H_ * COUT_) + h * COUT_ + c] = o;
}

// ---------------------------------------------------------------------------
extern "C" void kernel_launch(void* const* d_in, const int* in_sizes, int n_in,
                              void* d_out, int out_size) {
    const float* x    = (const float*)d_in[0];   // [B,N,CIN]
    const int*   adj  = (const int*)  d_in[1];   // [B,N,N]
    const float* W    = (const float*)d_in[2];   // [H,COUT,CIN] -> Wf [512,256]
    const float* a    = (const float*)d_in[3];   // [H,2,COUT]
    const float* bias = (const float*)d_in[4];   // [H,COUT]
    float* out = (float*)d_out;                  // [B,N,H*COUT]

    dim3 g1(N_ / 64, (H_ * COUT_) / 64, B_);
    gemm_hidden<<<g1, 256>>>(x, W);

    attn_scores<<<(B_ * H_ * N_) / 8, 256>>>(a);

    s2max_kernel<<<B_ * H_, 256>>>();

    dim3 g4(N_ / 16, H_, B_);
    attn_av<<<g4, 256>>>(adj, bias, out);
}

// round 3
// speedup vs baseline: 2.1649x; 2.1649x over previous
#include <cuda_runtime.h>
#include <cuda_bf16.h>

#define B_    4
#define N_    2048
#define CIN_  256
#define COUT_ 64
#define H_    8
#define ALPHA 0.2f

// Scratch (allocation-free rule: __device__ globals)
__device__ float g_hidden[(size_t)B_ * H_ * N_ * COUT_]; // 16.8 MB, [b][h][n][o]
__device__ float g_s1[B_ * H_ * N_];
__device__ float g_s2[B_ * H_ * N_];
__device__ float g_s2max[B_ * H_];

// ---------------------------------------------------------------------------
// Kernel 1: hidden[b,h,n,o] = sum_i x[b,n,i] * W[h,o,i]
// ---------------------------------------------------------------------------
__global__ void gemm_hidden(const float* __restrict__ x,
                            const float* __restrict__ Wf) {
    const int b    = blockIdx.z;
    const int m0   = blockIdx.x * 64;
    const int col0 = blockIdx.y * 64;          // == h*64
    __shared__ float As[32][68];
    __shared__ float Bs[32][68];
    const int t  = threadIdx.x;
    const int tx = t & 15, ty = t >> 4;
    float acc[4][4] = {};

    const float* xb = x + (size_t)b * N_ * CIN_;

    for (int k0 = 0; k0 < CIN_; k0 += 32) {
#pragma unroll
        for (int r = 0; r < 2; r++) {
            int fidx = t + r * 256;
            int row  = fidx >> 3;
            int c4   = (fidx & 7) * 4;
            float4 v = *(const float4*)&xb[(size_t)(m0 + row) * CIN_ + k0 + c4];
            As[c4 + 0][row] = v.x; As[c4 + 1][row] = v.y;
            As[c4 + 2][row] = v.z; As[c4 + 3][row] = v.w;
            float4 w = *(const float4*)&Wf[(size_t)(col0 + row) * CIN_ + k0 + c4];
            Bs[c4 + 0][row] = w.x; Bs[c4 + 1][row] = w.y;
            Bs[c4 + 2][row] = w.z; Bs[c4 + 3][row] = w.w;
        }
        __syncthreads();
#pragma unroll
        for (int kk = 0; kk < 32; kk++) {
            float4 rm = *(const float4*)&As[kk][ty * 4];
            float4 rn = *(const float4*)&Bs[kk][tx * 4];
            float am[4] = {rm.x, rm.y, rm.z, rm.w};
            float an[4] = {rn.x, rn.y, rn.z, rn.w};
#pragma unroll
            for (int i = 0; i < 4; i++)
#pragma unroll
                for (int j = 0; j < 4; j++)
                    acc[i][j] += am[i] * an[j];
        }
        __syncthreads();
    }

    const int h = col0 >> 6;
    float* dst = g_hidden + ((size_t)(b * H_ + h) * N_) * COUT_;
#pragma unroll
    for (int i = 0; i < 4; i++) {
        int m = m0 + ty * 4 + i;
        float4 o = make_float4(acc[i][0], acc[i][1], acc[i][2], acc[i][3]);
        *(float4*)&dst[(size_t)m * COUT_ + tx * 4] = o;
    }
}

// ---------------------------------------------------------------------------
// Kernel 2: s1/s2 row scores, one warp per (b,h,n)
// ---------------------------------------------------------------------------
__global__ void attn_scores(const float* __restrict__ a) {
    int gw   = blockIdx.x * 8 + (threadIdx.x >> 5);
    int lane = threadIdx.x & 31;
    int bh   = gw >> 11;
    int h    = bh & 7;
    const float* hrow = g_hidden + (size_t)gw * COUT_;
    float v0 = hrow[lane], v1 = hrow[lane + 32];
    const float* ah = a + h * 2 * COUT_;
    float p1 = v0 * ah[lane]      + v1 * ah[lane + 32];
    float p2 = v0 * ah[64 + lane] + v1 * ah[96 + lane];
#pragma unroll
    for (int off = 16; off > 0; off >>= 1) {
        p1 += __shfl_xor_sync(0xffffffff, p1, off);
        p2 += __shfl_xor_sync(0xffffffff, p2, off);
    }
    if (lane == 0) { g_s1[gw] = p1; g_s2[gw] = p2; }
}

// ---------------------------------------------------------------------------
// Kernel 3: per (b,h) unmasked max of s2
// ---------------------------------------------------------------------------
__global__ void s2max_kernel() {
    __shared__ float red[256];
    int bh = blockIdx.x;
    const float* s2 = g_s2 + bh * N_;
    float m = -1e30f;
    for (int j = threadIdx.x; j < N_; j += 256) m = fmaxf(m, s2[j]);
    red[threadIdx.x] = m;
    __syncthreads();
    for (int s = 128; s > 0; s >>= 1) {
        if (threadIdx.x < s) red[threadIdx.x] = fmaxf(red[threadIdx.x], red[threadIdx.x + s]);
        __syncthreads();
    }
    if (threadIdx.x == 0) g_s2max[bh] = red[0];
}

// ---------------------------------------------------------------------------
// Kernel 4 v2b: fused mask + softmax + AV, 4x4 register tiling.
// Block = 64 query rows x one (b,h). 256 threads.
// adj staged as bytes (values are 0/1) -> 4.25 KB, total smem ~38.5 KB.
// ---------------------------------------------------------------------------
__global__ void attn_av(const int* __restrict__ adj,
                        const float* __restrict__ bias,
                        float* __restrict__ out) {
    const int b  = blockIdx.z, h = blockIdx.y;
    const int i0 = blockIdx.x * 64;
    const int bh = b * H_ + h;

    __shared__ float hid_s[64][64];            // [jj][c]      16 KB
    __shared__ float wt_s[64][68];             // [jj][i] pad  17 KB (272B rows, 16B-mult)
    __shared__ unsigned char adj_s[64][68];    // [i][jj] pad  4.25 KB
    __shared__ float s1_s[64], M_s[64], wsum_s[64];

    const int t = threadIdx.x;
    if (t < 64) {
        float s1v = g_s1[bh * N_ + i0 + t];
        float e = s1v + g_s2max[bh];
        M_s[t]  = (e >= 0.f) ? e : ALPHA * e;   // leaky monotone: valid upper bound
        s1_s[t] = s1v;
        wsum_s[t] = 0.f;
    }
    __syncthreads();

    const int ty = t >> 4, tx = t & 15;
    float acc[4][4] = {};

    const float* hidbh = g_hidden + (size_t)bh * N_ * COUT_;
    const float* s2bh  = g_s2 + bh * N_;
    const int*   adjb  = adj + ((size_t)(b * N_ + i0)) * N_;

    const int wi  = t & 63;             // weight-phase row
    const int wj0 = (t >> 6) * 16;      // weight-phase jj base
    const float s1w = s1_s[wi];
    const float Mw  = M_s[wi];

    for (int j0 = 0; j0 < N_; j0 += 64) {
        // stage hidden tile [64 x 64] (coalesced float4)
#pragma unroll
        for (int r = 0; r < 4; r++) {
            int idx = t + r * 256;
            int row = idx >> 4, c4 = (idx & 15) * 4;
            *(float4*)&hid_s[row][c4] =
                *(const float4*)&hidbh[(size_t)(j0 + row) * COUT_ + c4];
        }
        // stage adj tile [64 x 64] (coalesced int4 -> packed uchar4 in smem)
#pragma unroll
        for (int r = 0; r < 4; r++) {
            int idx = t + r * 256;
            int row = idx >> 4, c4 = (idx & 15) * 4;
            int4 av = *(const int4*)&adjb[(size_t)row * N_ + j0 + c4];
            uchar4 pk;
            pk.x = (unsigned char)av.x; pk.y = (unsigned char)av.y;
            pk.z = (unsigned char)av.z; pk.w = (unsigned char)av.w;
            *(uchar4*)&adj_s[row][c4] = pk;
        }
        __syncthreads();

        // weights: thread owns row wi, jj in [wj0, wj0+16)
        float lsum = 0.f;
#pragma unroll
        for (int k = 0; k < 16; k++) {
            int jj = wj0 + k;
            float e = s1w + s2bh[j0 + jj];
            float l = (e >= 0.f) ? e : ALPHA * e;
            float w = (adj_s[wi][jj] > 0) ? __expf(l - Mw) : 0.f;
            wt_s[jj][wi] = w;                    // consecutive wi across lanes: no conflict
            lsum += w;
        }
        atomicAdd(&wsum_s[wi], lsum);            // spread addresses, cheap
        __syncthreads();

        // 4x4 register-tiled AV: 2 x LDS.128 -> 16 FFMA
#pragma unroll 8
        for (int jj = 0; jj < 64; jj++) {
            float4 wv = *(const float4*)&wt_s[jj][ty * 4];   // broadcast across tx
            float4 hv = *(const float4*)&hid_s[jj][tx * 4];  // broadcast across ty
            float w4[4] = {wv.x, wv.y, wv.z, wv.w};
#pragma unroll
            for (int ii = 0; ii < 4; ii++) {
                acc[ii][0] += w4[ii] * hv.x;
                acc[ii][1] += w4[ii] * hv.y;
                acc[ii][2] += w4[ii] * hv.z;
                acc[ii][3] += w4[ii] * hv.w;
            }
        }
        __syncthreads();
    }

    // epilogue: normalize, bias, relu
    float4 bv = *(const float4*)&bias[h * COUT_ + tx * 4];
#pragma unroll
    for (int ii = 0; ii < 4; ii++) {
        int i = ty * 4 + ii;
        float inv = 1.f / wsum_s[i];
        float4 o;
        o.x = fmaxf(acc[ii][0] * inv + bv.x, 0.f);
        o.y = fmaxf(acc[ii][1] * inv + bv.y, 0.f);
        o.z = fmaxf(acc[ii][2] * inv + bv.z, 0.f);
        o.w = fmaxf(acc[ii][3] * inv + bv.w, 0.f);
        *(float4*)&out[((size_t)(b * N_ + i0 + i)) * (H_ * COUT_) + h * COUT_ + tx * 4] = o;
    }
}

// ---------------------------------------------------------------------------
extern "C" void kernel_launch(void* const* d_in, const int* in_sizes, int n_in,
                              void* d_out, int out_size) {
    const float* x    = (const float*)d_in[0];   // [B,N,CIN]
    const int*   adj  = (const int*)  d_in[1];   // [B,N,N]
    const float* W    = (const float*)d_in[2];   // [H,COUT,CIN]
    const float* a    = (const float*)d_in[3];   // [H,2,COUT]
    const float* bias = (const float*)d_in[4];   // [H,COUT]
    float* out = (float*)d_out;                  // [B,N,H*COUT]

    dim3 g1(N_ / 64, (H_ * COUT_) / 64, B_);
    gemm_hidden<<<g1, 256>>>(x, W);

    attn_scores<<<(B_ * H_ * N_) / 8, 256>>>(a);

    s2max_kernel<<<B_ * H_, 256>>>();

    dim3 g4(N_ / 64, H_, B_);
    attn_av<<<g4, 256>>>(adj, bias, out);
}

// round 5
// speedup vs baseline: 2.9108x; 1.3446x over previous
#include <cuda_runtime.h>
#include <cuda_bf16.h>
#include <cstdint>

#define B_    4
#define N_    2048
#define CIN_  256
#define COUT_ 64
#define H_    8
#define ALPHA 0.2f

// ---------------- scratch (__device__ globals; no allocs allowed) -----------
__device__ float g_hidden[(size_t)B_ * H_ * N_ * COUT_];          // [bh][n][c] f32
__device__ __nv_bfloat16 g_hbf_hi[(size_t)B_ * H_ * N_ * COUT_];  // [bh][n][c]
__device__ __nv_bfloat16 g_hbf_lo[(size_t)B_ * H_ * N_ * COUT_];
__device__ float g_s1[B_ * H_ * N_];
__device__ float g_s2[B_ * H_ * N_];
__device__ float g_s2max[B_ * H_];
__device__ unsigned g_bits[(size_t)B_ * N_ * (N_ / 32)];          // adj bitmask

// ---------------- helpers (sm_80-era PTX only: ldmatrix + mma.sync) ---------
__device__ __forceinline__ uint32_t smem_u32(const void* p) {
    uint32_t a;
    asm("{ .reg .u64 t; cvta.to.shared.u64 t, %1; cvt.u32.u64 %0, t; }"
        : "=r"(a) : "l"(p));
    return a;
}
__device__ __forceinline__ uint32_t swz128(uint32_t off) {
    return off ^ ((off >> 3) & 0x70);
}
__device__ __forceinline__ void ldsm_x4(uint32_t* r, uint32_t addr) {
    asm volatile("ldmatrix.sync.aligned.m8n8.x4.shared.b16 {%0,%1,%2,%3}, [%4];"
                 : "=r"(r[0]), "=r"(r[1]), "=r"(r[2]), "=r"(r[3]) : "r"(addr));
}
__device__ __forceinline__ void ldsm_x4_t(uint32_t* r, uint32_t addr) {
    asm volatile("ldmatrix.sync.aligned.m8n8.x4.trans.shared.b16 {%0,%1,%2,%3}, [%4];"
                 : "=r"(r[0]), "=r"(r[1]), "=r"(r[2]), "=r"(r[3]) : "r"(addr));
}
__device__ __forceinline__ void mma_bf16(float* c, const uint32_t* a, const uint32_t* b) {
    asm volatile("mma.sync.aligned.m16n8k16.row.col.f32.bf16.bf16.f32 "
                 "{%0,%1,%2,%3}, {%4,%5,%6,%7}, {%8,%9}, {%0,%1,%2,%3};"
                 : "+f"(c[0]), "+f"(c[1]), "+f"(c[2]), "+f"(c[3])
                 : "r"(a[0]), "r"(a[1]), "r"(a[2]), "r"(a[3]), "r"(b[0]), "r"(b[1]));
}

// ---------------------------------------------------------------------------
// Kernel 1: hidden = x @ W^T ; epilogue also emits bf16 hi/lo split copies
// ---------------------------------------------------------------------------
__global__ void gemm_hidden(const float* __restrict__ x,
                            const float* __restrict__ Wf) {
    const int b    = blockIdx.z;
    const int m0   = blockIdx.x * 64;
    const int col0 = blockIdx.y * 64;
    __shared__ float As[32][68];
    __shared__ float Bs[32][68];
    const int t  = threadIdx.x;
    const int tx = t & 15, ty = t >> 4;
    float acc[4][4] = {};
    const float* xb = x + (size_t)b * N_ * CIN_;

    for (int k0 = 0; k0 < CIN_; k0 += 32) {
#pragma unroll
        for (int r = 0; r < 2; r++) {
            int fidx = t + r * 256;
            int row  = fidx >> 3;
            int c4   = (fidx & 7) * 4;
            float4 v = *(const float4*)&xb[(size_t)(m0 + row) * CIN_ + k0 + c4];
            As[c4 + 0][row] = v.x; As[c4 + 1][row] = v.y;
            As[c4 + 2][row] = v.z; As[c4 + 3][row] = v.w;
            float4 w = *(const float4*)&Wf[(size_t)(col0 + row) * CIN_ + k0 + c4];
            Bs[c4 + 0][row] = w.x; Bs[c4 + 1][row] = w.y;
            Bs[c4 + 2][row] = w.z; Bs[c4 + 3][row] = w.w;
        }
        __syncthreads();
#pragma unroll
        for (int kk = 0; kk < 32; kk++) {
            float4 rm = *(const float4*)&As[kk][ty * 4];
            float4 rn = *(const float4*)&Bs[kk][tx * 4];
            float am[4] = {rm.x, rm.y, rm.z, rm.w};
            float an[4] = {rn.x, rn.y, rn.z, rn.w};
#pragma unroll
            for (int i = 0; i < 4; i++)
#pragma unroll
                for (int j = 0; j < 4; j++)
                    acc[i][j] += am[i] * an[j];
        }
        __syncthreads();
    }
    const int h = col0 >> 6;
    const size_t base = ((size_t)(b * H_ + h) * N_);
#pragma unroll
    for (int i = 0; i < 4; i++) {
        int m = m0 + ty * 4 + i;
        size_t di = (base + m) * COUT_ + tx * 4;
        *(float4*)&g_hidden[di] =
            make_float4(acc[i][0], acc[i][1], acc[i][2], acc[i][3]);
        // bf16 hi/lo split
        __nv_bfloat16 b0 = __float2bfloat16(acc[i][0]);
        __nv_bfloat16 b1 = __float2bfloat16(acc[i][1]);
        __nv_bfloat16 b2 = __float2bfloat16(acc[i][2]);
        __nv_bfloat16 b3 = __float2bfloat16(acc[i][3]);
        __nv_bfloat162* hp = (__nv_bfloat162*)&g_hbf_hi[di];
        hp[0] = __halves2bfloat162(b0, b1);
        hp[1] = __halves2bfloat162(b2, b3);
        __nv_bfloat162* lp = (__nv_bfloat162*)&g_hbf_lo[di];
        lp[0] = __floats2bfloat162_rn(acc[i][0] - __bfloat162float(b0),
                                      acc[i][1] - __bfloat162float(b1));
        lp[1] = __floats2bfloat162_rn(acc[i][2] - __bfloat162float(b2),
                                      acc[i][3] - __bfloat162float(b3));
    }
}

// ---------------------------------------------------------------------------
// Kernel 2: s1/s2 row scores
// ---------------------------------------------------------------------------
__global__ void attn_scores(const float* __restrict__ a) {
    int gw   = blockIdx.x * 8 + (threadIdx.x >> 5);
    int lane = threadIdx.x & 31;
    int bh   = gw >> 11;
    int h    = bh & 7;
    const float* hrow = g_hidden + (size_t)gw * COUT_;
    float v0 = hrow[lane], v1 = hrow[lane + 32];
    const float* ah = a + h * 2 * COUT_;
    float p1 = v0 * ah[lane]      + v1 * ah[lane + 32];
    float p2 = v0 * ah[64 + lane] + v1 * ah[96 + lane];
#pragma unroll
    for (int off = 16; off > 0; off >>= 1) {
        p1 += __shfl_xor_sync(0xffffffff, p1, off);
        p2 += __shfl_xor_sync(0xffffffff, p2, off);
    }
    if (lane == 0) { g_s1[gw] = p1; g_s2[gw] = p2; }
}

// ---------------------------------------------------------------------------
// Kernel 3: per (b,h) unmasked max of s2
// ---------------------------------------------------------------------------
__global__ void s2max_kernel() {
    __shared__ float red[256];
    int bh = blockIdx.x;
    const float* s2 = g_s2 + bh * N_;
    float m = -1e30f;
    for (int j = threadIdx.x; j < N_; j += 256) m = fmaxf(m, s2[j]);
    red[threadIdx.x] = m;
    __syncthreads();
    for (int s = 128; s > 0; s >>= 1) {
        if (threadIdx.x < s) red[threadIdx.x] = fmaxf(red[threadIdx.x], red[threadIdx.x + s]);
        __syncthreads();
    }
    if (threadIdx.x == 0) g_s2max[bh] = red[0];
}

// ---------------------------------------------------------------------------
// Kernel 3b: adj -> bitmask (one warp per row)
// ---------------------------------------------------------------------------
__global__ void adj_bits_k(const int* __restrict__ adj) {
    int wid  = threadIdx.x >> 5, lane = threadIdx.x & 31;
    int row  = blockIdx.x * 8 + wid;                  // over B_*N_
    const int* ap = adj + (size_t)row * N_;
    unsigned* bp  = g_bits + (size_t)row * (N_ / 32);
    for (int w = 0; w < N_ / 32; w++) {
        int v = ap[w * 32 + lane];
        unsigned m = __ballot_sync(0xffffffffu, v > 0);
        if (lane == 0) bp[w] = m;
    }
}

// ---------------------------------------------------------------------------
// Kernel 4 v4: HMMA (mma.sync bf16, 3-term hi/lo split) AV.
// CTA = 128 query rows x (b,h); 8 warps; warp w owns rows w*16..+15, all 64 ch.
// ---------------------------------------------------------------------------
#define OFF_AHI  0          // [128][64] bf16 SW128 rows  16 KB
#define OFF_ALO  16384
#define OFF_BHI  32768      // [64][64]  bf16 SW128 rows   8 KB
#define OFF_BLO  40960
#define OFF_WSUM 49152      // float[128]
#define OFF_S2   49664      // float[64]
#define OFF_BIAS 49920      // float[64]
#define SMEM_TOTAL 50176

__global__ void __launch_bounds__(256) attn_av_mma(const float* __restrict__ bias,
                                                   float* __restrict__ out) {
    extern __shared__ char smem[];
    const uint32_t sb = smem_u32(smem);
    const int b = blockIdx.z, h = blockIdx.y, i0 = blockIdx.x * 128;
    const int bh = b * H_ + h;
    const int t = threadIdx.x, wid = t >> 5, lane = t & 31;

    float* wsum_s = (float*)(smem + OFF_WSUM);
    float* s2_s   = (float*)(smem + OFF_S2);
    float* bias_s = (float*)(smem + OFF_BIAS);
    if (t < 16) *(float4*)&bias_s[t * 4] = *(const float4*)&bias[h * COUT_ + t * 4];

    // weight-phase identity
    const int wrow = t >> 1, whalf = t & 1;
    const float s1i = g_s1[bh * N_ + i0 + wrow];
    float Mi;
    {
        float e = s1i + g_s2max[bh];
        Mi = (e >= 0.f) ? e : ALPHA * e;   // leaky monotone: valid upper bound
    }
    float rowsum = 0.f;

    const __nv_bfloat16* hHi = g_hbf_hi + (size_t)bh * N_ * COUT_;
    const __nv_bfloat16* hLo = g_hbf_lo + (size_t)bh * N_ * COUT_;
    const float* s2g = g_s2 + bh * N_;
    const unsigned* bitsb = g_bits + ((size_t)(b * N_ + i0)) * (N_ / 32);

    // ldmatrix lane-address components
    const int m0 = wid * 16;
    const int lrow = (lane & 7) + ((lane >> 3) & 1) * 8;
    const int lcol = (lane & 16) ? 16 : 0;
    const uint32_t aRowByte = (uint32_t)(m0 + lrow) * 128 + lcol;  // + ks*32
    // B: row = ks*16 + lrow ; colb = q*32 + lcol

    float acc[8][4] = {};

    for (int jt = 0; jt < 32; jt++) {
        const int j0 = jt * 64;
        __syncthreads();   // previous tile fully consumed

        // ---- stage B hi/lo tiles [64 k][64 n] (SW128 rows of 128B) ----
#pragma unroll
        for (int r = 0; r < 2; r++) {
            int idx = t + r * 256;
            int row = idx >> 3, ch = idx & 7;
            const size_t gsrc = (size_t)(j0 + row) * COUT_ + ch * 8;
            uint4 vh = *(const uint4*)(hHi + gsrc);
            uint4 vl = *(const uint4*)(hLo + gsrc);
            uint32_t so = swz128(row * 128 + ch * 16);
            *(uint4*)(smem + OFF_BHI + so) = vh;
            *(uint4*)(smem + OFF_BLO + so) = vl;
        }
        if (t < 16) *(float4*)&s2_s[t * 4] = *(const float4*)&s2g[j0 + t * 4];
        __syncthreads();   // s2_s visible

        // ---- weight phase: row wrow, jj in [whalf*32, whalf*32+32) ----
        {
            unsigned word = bitsb[(size_t)wrow * (N_ / 32) + jt * 2 + whalf];
            float lsum = 0.f;
#pragma unroll
            for (int c = 0; c < 4; c++) {
                uint32_t pk[4], pl[4];
#pragma unroll
                for (int u = 0; u < 4; u++) {
                    int k0 = c * 8 + u * 2;
                    float e0 = s1i + s2_s[whalf * 32 + k0];
                    float l0 = (e0 >= 0.f) ? e0 : ALPHA * e0;
                    float w0 = ((word >> k0) & 1u) ? __expf(l0 - Mi) : 0.f;
                    float e1 = s1i + s2_s[whalf * 32 + k0 + 1];
                    float l1 = (e1 >= 0.f) ? e1 : ALPHA * e1;
                    float w1 = ((word >> (k0 + 1)) & 1u) ? __expf(l1 - Mi) : 0.f;
                    lsum += w0 + w1;
                    __nv_bfloat16 b0 = __float2bfloat16(w0);
                    __nv_bfloat16 b1 = __float2bfloat16(w1);
                    __nv_bfloat162 hp = __halves2bfloat162(b0, b1);
                    __nv_bfloat162 lq =
                        __floats2bfloat162_rn(w0 - __bfloat162float(b0),
                                              w1 - __bfloat162float(b1));
                    pk[u] = *(uint32_t*)&hp;
                    pl[u] = *(uint32_t*)&lq;
                }
                uint32_t so = swz128(wrow * 128 + whalf * 64 + c * 16);
                *(uint4*)(smem + OFF_AHI + so) = make_uint4(pk[0], pk[1], pk[2], pk[3]);
                *(uint4*)(smem + OFF_ALO + so) = make_uint4(pl[0], pl[1], pl[2], pl[3]);
            }
            lsum += __shfl_xor_sync(0xffffffffu, lsum, 1);
            if (whalf == 0) rowsum += lsum;
        }
        __syncthreads();   // A tiles visible

        // ---- MMA: 4 ksteps x (2 A-terms) x 8 n-subtiles, 3-term split ----
#pragma unroll
        for (int ks = 0; ks < 4; ks++) {
            uint32_t ah[4], al[4];
            ldsm_x4(ah, sb + OFF_AHI + swz128(aRowByte + ks * 32));
            ldsm_x4(al, sb + OFF_ALO + swz128(aRowByte + ks * 32));
#pragma unroll
            for (int q = 0; q < 4; q++) {
                uint32_t bhf[4], blf[4];
                uint32_t boff = swz128((uint32_t)(ks * 16 + lrow) * 128 + q * 32 + lcol);
                ldsm_x4_t(bhf, sb + OFF_BHI + boff);
                ldsm_x4_t(blf, sb + OFF_BLO + boff);
#pragma unroll
                for (int s = 0; s < 2; s++) {
                    int nt = q * 2 + s;
                    mma_bf16(acc[nt], ah, &bhf[s * 2]);
                    mma_bf16(acc[nt], ah, &blf[s * 2]);
                    mma_bf16(acc[nt], al, &bhf[s * 2]);
                }
            }
        }
    }

    if (whalf == 0) wsum_s[wrow] = rowsum;
    __syncthreads();

    // ---- epilogue: normalize, bias, relu, store ----
    const int r0 = m0 + (lane >> 2);
    const int r1 = r0 + 8;
    const float inv0 = 1.f / wsum_s[r0];
    const float inv1 = 1.f / wsum_s[r1];
    float* op0 = out + ((size_t)(b * N_ + i0 + r0)) * (H_ * COUT_) + h * COUT_;
    float* op1 = out + ((size_t)(b * N_ + i0 + r1)) * (H_ * COUT_) + h * COUT_;
#pragma unroll
    for (int nt = 0; nt < 8; nt++) {
        int col = nt * 8 + (lane & 3) * 2;
        float bx = bias_s[col], by = bias_s[col + 1];
        float2 o0, o1;
        o0.x = fmaxf(acc[nt][0] * inv0 + bx, 0.f);
        o0.y = fmaxf(acc[nt][1] * inv0 + by, 0.f);
        o1.x = fmaxf(acc[nt][2] * inv1 + bx, 0.f);
        o1.y = fmaxf(acc[nt][3] * inv1 + by, 0.f);
        *(float2*)&op0[col] = o0;
        *(float2*)&op1[col] = o1;
    }
}

// ---------------------------------------------------------------------------
extern "C" void kernel_launch(void* const* d_in, const int* in_sizes, int n_in,
                              void* d_out, int out_size) {
    const float* x    = (const float*)d_in[0];
    const int*   adj  = (const int*)  d_in[1];
    const float* W    = (const float*)d_in[2];
    const float* a    = (const float*)d_in[3];
    const float* bias = (const float*)d_in[4];
    float* out = (float*)d_out;

    cudaFuncSetAttribute(attn_av_mma, cudaFuncAttributeMaxDynamicSharedMemorySize,
                         SMEM_TOTAL);

    adj_bits_k<<<(B_ * N_) / 8, 256>>>(adj);

    dim3 g1(N_ / 64, (H_ * COUT_) / 64, B_);
    gemm_hidden<<<g1, 256>>>(x, W);

    attn_scores<<<(B_ * H_ * N_) / 8, 256>>>(a);

    s2max_kernel<<<B_ * H_, 256>>>();

    dim3 g4(N_ / 128, H_, B_);
    attn_av_mma<<<g4, 256, SMEM_TOTAL>>>(bias, out);
}

// round 6
// speedup vs baseline: 4.2069x; 1.4453x over previous
#include <cuda_runtime.h>
#include <cuda_bf16.h>
#include <cstdint>

#define B_    4
#define N_    2048
#define CIN_  256
#define COUT_ 64
#define H_    8
#define ALPHA 0.2f

// ---------------- scratch (__device__ globals; no allocs allowed) -----------
__device__ float g_hidden[(size_t)B_ * H_ * N_ * COUT_];          // [bh][n][c] f32
__device__ __nv_bfloat16 g_hbf_hi[(size_t)B_ * H_ * N_ * COUT_];  // [bh][n][c]
__device__ __nv_bfloat16 g_hbf_lo[(size_t)B_ * H_ * N_ * COUT_];
__device__ float g_s1[B_ * H_ * N_];
__device__ float g_s2[B_ * H_ * N_];
__device__ float g_A1[B_ * H_ * N_];   // exp(s1 - M)
__device__ float g_A2[B_ * H_ * N_];   // exp(0.2 s1 - M)
__device__ float g_B1[B_ * H_ * N_];   // exp(s2)
__device__ float g_B2[B_ * H_ * N_];   // exp(0.2 s2)
__device__ unsigned g_bits[(size_t)B_ * N_ * (N_ / 32)];          // adj bitmask

// ---------------- helpers (sm_80-era PTX only) ------------------------------
__device__ __forceinline__ uint32_t smem_u32(const void* p) {
    uint32_t a;
    asm("{ .reg .u64 t; cvta.to.shared.u64 t, %1; cvt.u32.u64 %0, t; }"
        : "=r"(a) : "l"(p));
    return a;
}
__device__ __forceinline__ uint32_t swz128(uint32_t off) {
    return off ^ ((off >> 3) & 0x70);
}
__device__ __forceinline__ void ldsm_x4(uint32_t* r, uint32_t addr) {
    asm volatile("ldmatrix.sync.aligned.m8n8.x4.shared.b16 {%0,%1,%2,%3}, [%4];"
                 : "=r"(r[0]), "=r"(r[1]), "=r"(r[2]), "=r"(r[3]) : "r"(addr));
}
__device__ __forceinline__ void ldsm_x4_t(uint32_t* r, uint32_t addr) {
    asm volatile("ldmatrix.sync.aligned.m8n8.x4.trans.shared.b16 {%0,%1,%2,%3}, [%4];"
                 : "=r"(r[0]), "=r"(r[1]), "=r"(r[2]), "=r"(r[3]) : "r"(addr));
}
__device__ __forceinline__ void mma_bf16(float* c, const uint32_t* a, const uint32_t* b) {
    asm volatile("mma.sync.aligned.m16n8k16.row.col.f32.bf16.bf16.f32 "
                 "{%0,%1,%2,%3}, {%4,%5,%6,%7}, {%8,%9}, {%0,%1,%2,%3};"
                 : "+f"(c[0]), "+f"(c[1]), "+f"(c[2]), "+f"(c[3])
                 : "r"(a[0]), "r"(a[1]), "r"(a[2]), "r"(a[3]), "r"(b[0]), "r"(b[1]));
}
__device__ __forceinline__ void cp_async16(uint32_t dst, const void* src) {
    asm volatile("cp.async.cg.shared.global [%0], [%1], 16;"
                 :: "r"(dst), "l"(src) : "memory");
}
#define CP_COMMIT() asm volatile("cp.async.commit_group;" ::: "memory")
#define CP_WAIT0()  asm volatile("cp.async.wait_group 0;" ::: "memory")

// ---------------------------------------------------------------------------
// Kernel 1: hidden = x @ W^T ; epilogue emits f32 + bf16 hi/lo split
// ---------------------------------------------------------------------------
__global__ void gemm_hidden(const float* __restrict__ x,
                            const float* __restrict__ Wf) {
    const int b    = blockIdx.z;
    const int m0   = blockIdx.x * 64;
    const int col0 = blockIdx.y * 64;
    __shared__ float As[32][68];
    __shared__ float Bs[32][68];
    const int t  = threadIdx.x;
    const int tx = t & 15, ty = t >> 4;
    float acc[4][4] = {};
    const float* xb = x + (size_t)b * N_ * CIN_;

    for (int k0 = 0; k0 < CIN_; k0 += 32) {
#pragma unroll
        for (int r = 0; r < 2; r++) {
            int fidx = t + r * 256;
            int row  = fidx >> 3;
            int c4   = (fidx & 7) * 4;
            float4 v = *(const float4*)&xb[(size_t)(m0 + row) * CIN_ + k0 + c4];
            As[c4 + 0][row] = v.x; As[c4 + 1][row] = v.y;
            As[c4 + 2][row] = v.z; As[c4 + 3][row] = v.w;
            float4 w = *(const float4*)&Wf[(size_t)(col0 + row) * CIN_ + k0 + c4];
            Bs[c4 + 0][row] = w.x; Bs[c4 + 1][row] = w.y;
            Bs[c4 + 2][row] = w.z; Bs[c4 + 3][row] = w.w;
        }
        __syncthreads();
#pragma unroll
        for (int kk = 0; kk < 32; kk++) {
            float4 rm = *(const float4*)&As[kk][ty * 4];
            float4 rn = *(const float4*)&Bs[kk][tx * 4];
            float am[4] = {rm.x, rm.y, rm.z, rm.w};
            float an[4] = {rn.x, rn.y, rn.z, rn.w};
#pragma unroll
            for (int i = 0; i < 4; i++)
#pragma unroll
                for (int j = 0; j < 4; j++)
                    acc[i][j] += am[i] * an[j];
        }
        __syncthreads();
    }
    const int h = col0 >> 6;
    const size_t base = ((size_t)(b * H_ + h) * N_);
#pragma unroll
    for (int i = 0; i < 4; i++) {
        int m = m0 + ty * 4 + i;
        size_t di = (base + m) * COUT_ + tx * 4;
        *(float4*)&g_hidden[di] =
            make_float4(acc[i][0], acc[i][1], acc[i][2], acc[i][3]);
        __nv_bfloat16 b0 = __float2bfloat16(acc[i][0]);
        __nv_bfloat16 b1 = __float2bfloat16(acc[i][1]);
        __nv_bfloat16 b2 = __float2bfloat16(acc[i][2]);
        __nv_bfloat16 b3 = __float2bfloat16(acc[i][3]);
        __nv_bfloat162* hp = (__nv_bfloat162*)&g_hbf_hi[di];
        hp[0] = __halves2bfloat162(b0, b1);
        hp[1] = __halves2bfloat162(b2, b3);
        __nv_bfloat162* lp = (__nv_bfloat162*)&g_hbf_lo[di];
        lp[0] = __floats2bfloat162_rn(acc[i][0] - __bfloat162float(b0),
                                      acc[i][1] - __bfloat162float(b1));
        lp[1] = __floats2bfloat162_rn(acc[i][2] - __bfloat162float(b2),
                                      acc[i][3] - __bfloat162float(b3));
    }
}

// ---------------------------------------------------------------------------
// Kernel 2: s1/s2 row scores
// ---------------------------------------------------------------------------
__global__ void attn_scores(const float* __restrict__ a) {
    int gw   = blockIdx.x * 8 + (threadIdx.x >> 5);
    int lane = threadIdx.x & 31;
    int bh   = gw >> 11;
    int h    = bh & 7;
    const float* hrow = g_hidden + (size_t)gw * COUT_;
    float v0 = hrow[lane], v1 = hrow[lane + 32];
    const float* ah = a + h * 2 * COUT_;
    float p1 = v0 * ah[lane]      + v1 * ah[lane + 32];
    float p2 = v0 * ah[64 + lane] + v1 * ah[96 + lane];
#pragma unroll
    for (int off = 16; off > 0; off >>= 1) {
        p1 += __shfl_xor_sync(0xffffffff, p1, off);
        p2 += __shfl_xor_sync(0xffffffff, p2, off);
    }
    if (lane == 0) { g_s1[gw] = p1; g_s2[gw] = p2; }
}

// ---------------------------------------------------------------------------
// Kernel 3: per (b,h): s2max reduce, then exp factor precompute.
//   M_i = leaky(s1_i + s2max); A1=exp(s1-M), A2=exp(.2 s1-M), B1=exp(s2), B2=exp(.2 s2)
// ---------------------------------------------------------------------------
__global__ void row_factors() {
    __shared__ float red[256];
    __shared__ float s2max_s;
    int bh = blockIdx.x;
    const float* s1 = g_s1 + bh * N_;
    const float* s2 = g_s2 + bh * N_;
    float m = -1e30f;
    for (int j = threadIdx.x; j < N_; j += 256) m = fmaxf(m, s2[j]);
    red[threadIdx.x] = m;
    __syncthreads();
    for (int s = 128; s > 0; s >>= 1) {
        if (threadIdx.x < s) red[threadIdx.x] = fmaxf(red[threadIdx.x], red[threadIdx.x + s]);
        __syncthreads();
    }
    if (threadIdx.x == 0) s2max_s = red[0];
    __syncthreads();
    const float s2m = s2max_s;
    for (int j = threadIdx.x; j < N_; j += 256) {
        float s1v = s1[j], s2v = s2[j];
        float e = s1v + s2m;
        float M = (e >= 0.f) ? e : ALPHA * e;
        g_A1[bh * N_ + j] = __expf(s1v - M);
        g_A2[bh * N_ + j] = __expf(ALPHA * s1v - M);
        g_B1[bh * N_ + j] = __expf(s2v);
        g_B2[bh * N_ + j] = __expf(ALPHA * s2v);
    }
}

// ---------------------------------------------------------------------------
// Kernel 3b: adj -> bitmask
// ---------------------------------------------------------------------------
__global__ void adj_bits_k(const int* __restrict__ adj) {
    int wid  = threadIdx.x >> 5, lane = threadIdx.x & 31;
    int row  = blockIdx.x * 8 + wid;                  // over B_*N_
    const int* ap = adj + (size_t)row * N_;
    unsigned* bp  = g_bits + (size_t)row * (N_ / 32);
    for (int w = 0; w < N_ / 32; w++) {
        int v = ap[w * 32 + lane];
        unsigned m = __ballot_sync(0xffffffffu, v > 0);
        if (lane == 0) bp[w] = m;
    }
}

// ---------------------------------------------------------------------------
// Kernel 4 v5: HMMA AV, factorized-exp weight phase (no MUFU), cp.async B.
// CTA = 128 query rows x (b,h); 8 warps.
// ---------------------------------------------------------------------------
#define OFF_AHI  0          // [128][64] bf16 SW128  16 KB
#define OFF_ALO  16384
#define OFF_BHI  32768      // [64][64]  bf16 SW128   8 KB
#define OFF_BLO  40960
#define OFF_S2F  49152      // float[2048]            8 KB
#define OFF_B1F  57344      // float[2048]            8 KB
#define OFF_B2F  65536      // float[2048]            8 KB
#define OFF_WSUM 73728      // float[128]
#define OFF_BIAS 74240      // float[64]
#define SMEM_TOTAL 74752

__global__ void __launch_bounds__(256) attn_av_mma(const float* __restrict__ bias,
                                                   float* __restrict__ out) {
    extern __shared__ char smem[];
    const uint32_t sb = smem_u32(smem);
    const int b = blockIdx.z, h = blockIdx.y, i0 = blockIdx.x * 128;
    const int bh = b * H_ + h;
    const int t = threadIdx.x, wid = t >> 5, lane = t & 31;

    float* wsum_s = (float*)(smem + OFF_WSUM);
    float* s2f    = (float*)(smem + OFF_S2F);
    float* b1f    = (float*)(smem + OFF_B1F);
    float* b2f    = (float*)(smem + OFF_B2F);
    float* bias_s = (float*)(smem + OFF_BIAS);
    if (t < 16) *(float4*)&bias_s[t * 4] = *(const float4*)&bias[h * COUT_ + t * 4];

    // prologue: stage full per-j factor arrays (2048 each)
    {
        const float* s2g = g_s2 + bh * N_;
        const float* B1g = g_B1 + bh * N_;
        const float* B2g = g_B2 + bh * N_;
#pragma unroll
        for (int r = 0; r < 2; r++) {
            int q = (t + r * 256) * 4;
            *(float4*)&s2f[q] = *(const float4*)&s2g[q];
            *(float4*)&b1f[q] = *(const float4*)&B1g[q];
            *(float4*)&b2f[q] = *(const float4*)&B2g[q];
        }
    }

    // weight-phase identity: thread -> row wrow, half whalf (32 j's)
    const int wrow = t >> 1, whalf = t & 1;
    const float s1i = g_s1[bh * N_ + i0 + wrow];
    const float A1  = g_A1[bh * N_ + i0 + wrow];
    const float A2  = g_A2[bh * N_ + i0 + wrow];
    float rowsum = 0.f;

    const __nv_bfloat16* hHi = g_hbf_hi + (size_t)bh * N_ * COUT_;
    const __nv_bfloat16* hLo = g_hbf_lo + (size_t)bh * N_ * COUT_;
    const unsigned* bitsb = g_bits + ((size_t)(b * N_ + i0)) * (N_ / 32);
    unsigned wordv = bitsb[(size_t)wrow * (N_ / 32) + whalf];

    // ldmatrix lane addressing
    const int m0 = wid * 16;
    const int lrow = (lane & 7) + ((lane >> 3) & 1) * 8;
    const int lcol = (lane & 16) ? 16 : 0;
    const uint32_t aRowByte = (uint32_t)(m0 + lrow) * 128 + lcol;

    float acc[8][4] = {};

    for (int jt = 0; jt < 32; jt++) {
        const int j0 = jt * 64;
        __syncthreads();   // prior MMA consumed tiles; prologue visible

        // ---- B tiles via cp.async (overlaps with weight phase) ----
#pragma unroll
        for (int r = 0; r < 2; r++) {
            int idx = t + r * 256;
            int row = idx >> 3, ch = idx & 7;
            const size_t gsrc = (size_t)(j0 + row) * COUT_ + ch * 8;
            uint32_t so = swz128(row * 128 + ch * 16);
            cp_async16(sb + OFF_BHI + so, hHi + gsrc);
            cp_async16(sb + OFF_BLO + so, hLo + gsrc);
        }
        CP_COMMIT();

        // ---- weight phase: no exp, no cvt-to-f32; truncation hi/lo split ----
        {
            const int jb = j0 + whalf * 32;
            float lsum = 0.f;
#pragma unroll
            for (int c = 0; c < 4; c++) {
                uint32_t pk[4], pl[4];
#pragma unroll
                for (int u = 0; u < 4; u++) {
                    int k0 = c * 8 + u * 2;
                    float s2v0 = s2f[jb + k0],     f10 = b1f[jb + k0],     f20 = b2f[jb + k0];
                    float s2v1 = s2f[jb + k0 + 1], f11 = b1f[jb + k0 + 1], f21 = b2f[jb + k0 + 1];
                    bool p0 = (s1i + s2v0) >= 0.f;
                    bool p1 = (s1i + s2v1) >= 0.f;
                    float w0 = (p0 ? A1 : A2) * (p0 ? f10 : f20);
                    float w1 = (p1 ? A1 : A2) * (p1 ? f11 : f21);
                    int kk = whalf * 32 + k0;   // bit index base (word covers 32 j)
                    // NOTE: wordv is per-half-row: bit k of wordv <-> j = jb + k
                    w0 = ((wordv >> k0) & 1u) ? w0 : 0.f;
                    w1 = ((wordv >> (k0 + 1)) & 1u) ? w1 : 0.f;
                    (void)kk;
                    lsum += w0 + w1;
                    uint32_t u0 = __float_as_uint(w0), u1 = __float_as_uint(w1);
                    uint32_t h0 = u0 & 0xFFFF0000u, h1 = u1 & 0xFFFF0000u;
                    pk[u] = __byte_perm(h0, h1, 0x7632);   // {bf16(w1),bf16(w0)}
                    float l0 = w0 - __uint_as_float(h0);
                    float l1 = w1 - __uint_as_float(h1);
                    __nv_bfloat162 lq = __floats2bfloat162_rn(l0, l1);
                    pl[u] = *(uint32_t*)&lq;
                }
                uint32_t so = swz128(wrow * 128 + whalf * 64 + c * 16);
                *(uint4*)(smem + OFF_AHI + so) = make_uint4(pk[0], pk[1], pk[2], pk[3]);
                *(uint4*)(smem + OFF_ALO + so) = make_uint4(pl[0], pl[1], pl[2], pl[3]);
            }
            lsum += __shfl_xor_sync(0xffffffffu, lsum, 1);
            if (whalf == 0) rowsum += lsum;
        }

        // prefetch next adj word (latency hidden by MMA phase)
        unsigned word_next = (jt < 31)
            ? bitsb[(size_t)wrow * (N_ / 32) + (jt + 1) * 2 + whalf] : 0u;

        CP_WAIT0();
        __syncthreads();   // A tiles + B tiles ready

        // ---- MMA: 4 ksteps x 4 q x 2 s x 3 split terms ----
#pragma unroll
        for (int ks = 0; ks < 4; ks++) {
            uint32_t ah[4], al[4];
            ldsm_x4(ah, sb + OFF_AHI + swz128(aRowByte + ks * 32));
            ldsm_x4(al, sb + OFF_ALO + swz128(aRowByte + ks * 32));
#pragma unroll
            for (int q = 0; q < 4; q++) {
                uint32_t bhf[4], blf[4];
                uint32_t boff = swz128((uint32_t)(ks * 16 + lrow) * 128 + q * 32 + lcol);
                ldsm_x4_t(bhf, sb + OFF_BHI + boff);
                ldsm_x4_t(blf, sb + OFF_BLO + boff);
#pragma unroll
                for (int s = 0; s < 2; s++) {
                    int nt = q * 2 + s;
                    mma_bf16(acc[nt], ah, &bhf[s * 2]);
                    mma_bf16(acc[nt], ah, &blf[s * 2]);
                    mma_bf16(acc[nt], al, &bhf[s * 2]);
                }
            }
        }
        wordv = word_next;
    }

    if (whalf == 0) wsum_s[wrow] = rowsum;
    __syncthreads();

    // ---- epilogue ----
    const int r0 = m0 + (lane >> 2);
    const int r1 = r0 + 8;
    const float inv0 = 1.f / wsum_s[r0];
    const float inv1 = 1.f / wsum_s[r1];
    float* op0 = out + ((size_t)(b * N_ + i0 + r0)) * (H_ * COUT_) + h * COUT_;
    float* op1 = out + ((size_t)(b * N_ + i0 + r1)) * (H_ * COUT_) + h * COUT_;
#pragma unroll
    for (int nt = 0; nt < 8; nt++) {
        int col = nt * 8 + (lane & 3) * 2;
        float bx = bias_s[col], by = bias_s[col + 1];
        float2 o0, o1;
        o0.x = fmaxf(acc[nt][0] * inv0 + bx, 0.f);
        o0.y = fmaxf(acc[nt][1] * inv0 + by, 0.f);
        o1.x = fmaxf(acc[nt][2] * inv1 + bx, 0.f);
        o1.y = fmaxf(acc[nt][3] * inv1 + by, 0.f);
        *(float2*)&op0[col] = o0;
        *(float2*)&op1[col] = o1;
    }
}

// ---------------------------------------------------------------------------
extern "C" void kernel_launch(void* const* d_in, const int* in_sizes, int n_in,
                              void* d_out, int out_size) {
    const float* x    = (const float*)d_in[0];
    const int*   adj  = (const int*)  d_in[1];
    const float* W    = (const float*)d_in[2];
    const float* a    = (const float*)d_in[3];
    const float* bias = (const float*)d_in[4];
    float* out = (float*)d_out;

    cudaFuncSetAttribute(attn_av_mma, cudaFuncAttributeMaxDynamicSharedMemorySize,
                         SMEM_TOTAL);

    adj_bits_k<<<(B_ * N_) / 8, 256>>>(adj);

    dim3 g1(N_ / 64, (H_ * COUT_) / 64, B_);
    gemm_hidden<<<g1, 256>>>(x, W);

    attn_scores<<<(B_ * H_ * N_) / 8, 256>>>(a);

    row_factors<<<B_ * H_, 256>>>();

    dim3 g4(N_ / 128, H_, B_);
    attn_av_mma<<<g4, 256, SMEM_TOTAL>>>(bias, out);
}